// round 2
// baseline (speedup 1.0000x reference)
#include <cuda_runtime.h>
#include <math.h>

#define T_ 256
#define N_ 64
#define C_ 4096
#define L_ 32
#define S_ 65           // 2*L+1
#define BLANK_ 0
#define NEGV -1e30f

// Scratch: lp_ext[T][N][S] (+pad for harmless OOB lane reads) and per-batch nll
__device__ float g_lp_ext[T_ * N_ * S_ + 64];
__device__ float g_per_n[N_];

// Kernel 1: per (t,n) row of 4096 -> logsumexp, then gather the 65 extended-label
// log-probs into g_lp_ext. Reads preds exactly once; at HBM roofline already.
__global__ void __launch_bounds__(256) lse_gather_kernel(
    const float* __restrict__ preds, const int* __restrict__ targets)
{
    const int row = blockIdx.x;        // row = t*N + n  (preds is (T,N,C) row-major)
    const int n   = row % N_;
    const float* __restrict__ p = preds + (size_t)row * C_;
    const int tid = threadIdx.x;

    float v[16];
    const float4* __restrict__ p4 = (const float4*)p;
    #pragma unroll
    for (int k = 0; k < 4; k++) {
        float4 f = p4[tid + k * 256];
        v[k*4+0] = f.x; v[k*4+1] = f.y; v[k*4+2] = f.z; v[k*4+3] = f.w;
    }

    // block max
    float m = v[0];
    #pragma unroll
    for (int i = 1; i < 16; i++) m = fmaxf(m, v[i]);
    #pragma unroll
    for (int o = 16; o > 0; o >>= 1) m = fmaxf(m, __shfl_xor_sync(0xffffffffu, m, o));
    __shared__ float sm[8];
    if ((tid & 31) == 0) sm[tid >> 5] = m;
    __syncthreads();
    float bm = sm[0];
    #pragma unroll
    for (int i = 1; i < 8; i++) bm = fmaxf(bm, sm[i]);
    __syncthreads();   // sm reused below

    // block sum of exp (full-precision expf: this feeds the normalizer, keep exact)
    float s = 0.0f;
    #pragma unroll
    for (int i = 0; i < 16; i++) s += expf(v[i] - bm);
    #pragma unroll
    for (int o = 16; o > 0; o >>= 1) s += __shfl_xor_sync(0xffffffffu, s, o);
    if ((tid & 31) == 0) sm[tid >> 5] = s;
    __syncthreads();
    float bs = sm[0];
    #pragma unroll
    for (int i = 1; i < 8; i++) bs += sm[i];

    const float lse = bm + logf(bs);

    // gather extended labels: even s -> blank(0), odd s -> targets[n][(s-1)/2]
    if (tid < S_) {
        int label = (tid & 1) ? targets[n * L_ + (tid >> 1)] : BLANK_;
        g_lp_ext[row * S_ + tid] = p[label] - lse;   // L2 hit (row just streamed)
    }
}

// Fused 3-way logaddexp via MUFU (EX2/LG2). Handles -1e30 sentinels correctly:
// exp(NEG - finite) underflows to 0; all-NEG gives NEG + log(3) ~= NEG.
__device__ __forceinline__ float lae3(float a1, float a2, float a3) {
    float m = fmaxf(fmaxf(a1, a2), a3);
    float e = __expf(a1 - m) + __expf(a2 - m) + __expf(a3 - m);
    return m + __logf(e);
}

__device__ __forceinline__ float lae2(float a, float b) {
    float m = fmaxf(a, b);
    return m + __logf(__expf(a - m) + __expf(b - m));
}

// Kernel 2: CTC forward recursion, one WARP per batch element.
// Lane l owns states {3l, 3l+1, 3l+2}; cross-lane deps via two shfl_up per step.
// lp for step t+1 is prefetched during step t. No shared memory, no barriers.
__global__ void __launch_bounds__(128) ctc_forward_kernel(
    const int* __restrict__ targets,
    const int* __restrict__ pred_lengths,
    const int* __restrict__ target_lengths)
{
    const int warp = threadIdx.x >> 5;
    const int lane = threadIdx.x & 31;
    const int n    = blockIdx.x * 4 + warp;
    const unsigned FULL = 0xffffffffu;

    const int tl = target_lengths[n];
    const int pl = pred_lengths[n];
    const int Sv = 2 * tl + 1;
    const int s0 = 3 * lane;

    bool valid[3], skip[3];
    #pragma unroll
    for (int j = 0; j < 3; j++) {
        int s = s0 + j;
        valid[j] = (s < S_) && (s < Sv);
        bool sk = false;
        if (s < S_ && (s & 1) && s >= 2) {
            int lab  = targets[n * L_ + (s >> 1)];
            int lab2 = targets[n * L_ + (s >> 1) - 1];
            sk = (lab != BLANK_) && (lab != lab2);
        }
        skip[j] = sk;
    }

    const float* __restrict__ lp_n = g_lp_ext + n * S_;   // + t*N_*S_ per step
    const int tstride = N_ * S_;

    // alpha0
    float alpha[3];
    {
        float l0 = lp_n[0];
        float l1 = lp_n[1];
        #pragma unroll
        for (int j = 0; j < 3; j++) {
            int s = s0 + j;
            float a0 = NEGV;
            if (s == 0) a0 = l0;
            if (s == 1 && tl > 0) a0 = l1;
            alpha[j] = valid[j] ? a0 : NEGV;
        }
    }

    // prefetch lp for t=1
    float lp[3];
    {
        const float* r = lp_n + tstride;
        lp[0] = r[s0]; lp[1] = r[s0 + 1]; lp[2] = r[s0 + 2];
    }

    for (int t = 1; t < T_; t++) {
        // prefetch t+1
        float lpn0 = 0.f, lpn1 = 0.f, lpn2 = 0.f;
        if (t + 1 < T_) {
            const float* r = lp_n + (t + 1) * tstride;
            lpn0 = r[s0]; lpn1 = r[s0 + 1]; lpn2 = r[s0 + 2];
        }

        float nb1 = __shfl_up_sync(FULL, alpha[1], 1);  // state 3(l-1)+1 = s0-2
        float nb2 = __shfl_up_sync(FULL, alpha[2], 1);  // state 3(l-1)+2 = s0-1
        if (lane == 0) { nb1 = NEGV; nb2 = NEGV; }

        float c0 = lae3(alpha[0], nb2,      skip[0] ? nb1      : NEGV);
        float c1 = lae3(alpha[1], alpha[0], skip[1] ? nb2      : NEGV);
        float c2 = lae3(alpha[2], alpha[1], skip[2] ? alpha[0] : NEGV);

        if (t < pl) {
            alpha[0] = valid[0] ? (c0 + lp[0]) : NEGV;
            alpha[1] = valid[1] ? (c1 + lp[1]) : NEGV;
            alpha[2] = valid[2] ? (c2 + lp[2]) : NEGV;
        }
        lp[0] = lpn0; lp[1] = lpn1; lp[2] = lpn2;
    }

    // extract alpha[end] and alpha[end-1] (end = 2*tl, uniform within warp)
    const int end = 2 * tl;
    const int le = end / 3, je = end % 3;
    float v0 = __shfl_sync(FULL, alpha[0], le);
    float v1 = __shfl_sync(FULL, alpha[1], le);
    float v2 = __shfl_sync(FULL, alpha[2], le);
    float a_last = (je == 0) ? v0 : (je == 1) ? v1 : v2;

    const int ep = (end > 0) ? end - 1 : 0;
    const int lp_lane = ep / 3, jp = ep % 3;
    float w0 = __shfl_sync(FULL, alpha[0], lp_lane);
    float w1 = __shfl_sync(FULL, alpha[1], lp_lane);
    float w2 = __shfl_sync(FULL, alpha[2], lp_lane);
    float a_prev = (jp == 0) ? w0 : (jp == 1) ? w1 : w2;
    if (tl <= 0) a_prev = NEGV;

    if (lane == 0) {
        float nll = -lae2(a_last, a_prev);
        if (!isfinite(nll) || nll >= 1e29f) nll = 0.0f;
        int denom = tl > 0 ? tl : 1;
        g_per_n[n] = nll / (float)denom;
    }
}

// Kernel 3: mean over N
__global__ void __launch_bounds__(64) finalize_kernel(float* __restrict__ out)
{
    const int tid = threadIdx.x;
    float v = g_per_n[tid];
    #pragma unroll
    for (int o = 16; o > 0; o >>= 1) v += __shfl_xor_sync(0xffffffffu, v, o);
    __shared__ float sw[2];
    if ((tid & 31) == 0) sw[tid >> 5] = v;
    __syncthreads();
    if (tid == 0) out[0] = (sw[0] + sw[1]) / (float)N_;
}

extern "C" void kernel_launch(void* const* d_in, const int* in_sizes, int n_in,
                              void* d_out, int out_size)
{
    const float* preds          = (const float*)d_in[0];
    const int*   targets        = (const int*)d_in[1];
    const int*   pred_lengths   = (const int*)d_in[2];
    const int*   target_lengths = (const int*)d_in[3];
    float* out = (float*)d_out;

    lse_gather_kernel<<<T_ * N_, 256>>>(preds, targets);
    ctc_forward_kernel<<<N_ / 4, 128>>>(targets, pred_lengths, target_lengths);
    finalize_kernel<<<1, 64>>>(out);
}

// round 3
// speedup vs baseline: 1.6355x; 1.6355x over previous
#include <cuda_runtime.h>
#include <math.h>

#define T_ 256
#define N_ 64
#define C_ 4096
#define L_ 32
#define S_ 65           // 2*L+1
#define BLANK_ 0
#define NEGV -1e30f
#define LOG2E 1.4426950408889634f
#define LN2   0.6931471805599453f

#define TP_ (T_ + 8)    // padded T so the depth-4 pipeline never loads OOB

// Scratch, layout [n][t][s] (n-major so each warp's stream is contiguous in t)
__device__ float g_lp_ext[N_ * TP_ * S_ + 128];
__device__ float g_per_n[N_];

__device__ __forceinline__ float ex2(float x) {
    float y; asm("ex2.approx.ftz.f32 %0, %1;" : "=f"(y) : "f"(x)); return y;
}
__device__ __forceinline__ float lg2(float x) {
    float y; asm("lg2.approx.ftz.f32 %0, %1;" : "=f"(y) : "f"(x)); return y;
}

// Kernel 1: per (t,n) row of 4096 -> logsumexp, then gather 65 extended-label
// log-probs (in log2 domain) into g_lp_ext[n][t][s]. Reads preds exactly once.
__global__ void __launch_bounds__(256) lse_gather_kernel(
    const float* __restrict__ preds, const int* __restrict__ targets)
{
    const int row = blockIdx.x;        // row = t*N + n  (preds is (T,N,C))
    const int t   = row / N_;
    const int n   = row % N_;
    const float* __restrict__ p = preds + (size_t)row * C_;
    const int tid = threadIdx.x;

    float v[16];
    const float4* __restrict__ p4 = (const float4*)p;
    #pragma unroll
    for (int k = 0; k < 4; k++) {
        float4 f = p4[tid + k * 256];
        v[k*4+0] = f.x; v[k*4+1] = f.y; v[k*4+2] = f.z; v[k*4+3] = f.w;
    }

    // block max
    float m = v[0];
    #pragma unroll
    for (int i = 1; i < 16; i++) m = fmaxf(m, v[i]);
    #pragma unroll
    for (int o = 16; o > 0; o >>= 1) m = fmaxf(m, __shfl_xor_sync(0xffffffffu, m, o));
    __shared__ float sm[8];
    if ((tid & 31) == 0) sm[tid >> 5] = m;
    __syncthreads();
    float bm = sm[0];
    #pragma unroll
    for (int i = 1; i < 8; i++) bm = fmaxf(bm, sm[i]);
    __syncthreads();   // sm reused below

    // block sum of exp via EX2 (1 FMA + 1 MUFU per element)
    const float bmL = bm * LOG2E;
    float s = 0.0f;
    #pragma unroll
    for (int i = 0; i < 16; i++) s += ex2(fmaf(v[i], LOG2E, -bmL));
    #pragma unroll
    for (int o = 16; o > 0; o >>= 1) s += __shfl_xor_sync(0xffffffffu, s, o);
    if ((tid & 31) == 0) sm[tid >> 5] = s;
    __syncthreads();
    float bs = sm[0];
    #pragma unroll
    for (int i = 1; i < 8; i++) bs += sm[i];

    const float lse = bm + lg2(bs) * LN2;

    // gather; store log2-scaled: (logp) * LOG2E
    if (tid < S_) {
        int label = (tid & 1) ? targets[n * L_ + (tid >> 1)] : BLANK_;
        g_lp_ext[(n * TP_ + t) * S_ + tid] = (p[label] - lse) * LOG2E;
    }
}

// 3-way logaddexp in log2 domain (raw EX2/LG2). NEG sentinels: ex2(NEG-m)=0;
// all-NEG gives NEG + log2(3) ~= NEG.
__device__ __forceinline__ float lae3_2(float a, float b, float c) {
    float m = fmaxf(fmaxf(a, b), c);
    float e = ex2(a - m) + ex2(b - m) + ex2(c - m);
    return m + lg2(e);
}
__device__ __forceinline__ float lae2_2(float a, float b) {
    float m = fmaxf(a, b);
    return m + lg2(ex2(a - m) + ex2(b - m));
}

// Kernel 2: CTC forward recursion, one WARP per batch element, log2 domain.
// Lane l owns states {3l,3l+1,3l+2}. Depth-4 register pipeline on the lp stream
// hides the ~260-cyc L2 latency. 256 iterations (unroll 4, static reg indexing).
__global__ void __launch_bounds__(128) ctc_forward_kernel(
    const int* __restrict__ targets,
    const int* __restrict__ pred_lengths,
    const int* __restrict__ target_lengths)
{
    const int warp = threadIdx.x >> 5;
    const int lane = threadIdx.x & 31;
    const int n    = blockIdx.x * 4 + warp;
    const unsigned FULL = 0xffffffffu;

    const int tl = target_lengths[n];
    const int pl = pred_lengths[n];
    const int Sv = 2 * tl + 1;
    const int s0 = 3 * lane;

    bool valid[3], skip[3];
    #pragma unroll
    for (int j = 0; j < 3; j++) {
        int s = s0 + j;
        valid[j] = (s < S_) && (s < Sv);
        bool sk = false;
        if (s < S_ && (s & 1) && s >= 2) {
            int lab  = targets[n * L_ + (s >> 1)];
            int lab2 = targets[n * L_ + (s >> 1) - 1];
            sk = (lab != BLANK_) && (lab != lab2);
        }
        skip[j] = sk;
    }

    const float* __restrict__ lp_n = g_lp_ext + n * (TP_ * S_);

    // alpha0 (log2 domain)
    float alpha[3];
    {
        float l0 = lp_n[0];
        float l1 = lp_n[1];
        #pragma unroll
        for (int j = 0; j < 3; j++) {
            int s = s0 + j;
            float a0 = NEGV;
            if (s == 0) a0 = l0;
            if (s == 1 && tl > 0) a0 = l1;
            alpha[j] = valid[j] ? a0 : NEGV;
        }
    }

    // preload pipeline: rows t = 1..4
    float lp[4][3];
    #pragma unroll
    for (int j = 0; j < 4; j++) {
        const float* r = lp_n + (1 + j) * S_ + s0;
        lp[j][0] = r[0]; lp[j][1] = r[1]; lp[j][2] = r[2];
    }

    #pragma unroll 4
    for (int t = 1; t <= 256; t++) {
        const int u = (t - 1) & 3;
        float l0 = lp[u][0], l1 = lp[u][1], l2 = lp[u][2];

        // refill slot with row t+4 (always in-bounds thanks to TP_ padding)
        {
            const float* r = lp_n + (t + 4) * S_ + s0;
            lp[u][0] = r[0]; lp[u][1] = r[1]; lp[u][2] = r[2];
        }

        float nb1 = __shfl_up_sync(FULL, alpha[1], 1);  // state s0-2
        float nb2 = __shfl_up_sync(FULL, alpha[2], 1);  // state s0-1
        if (lane == 0) { nb1 = NEGV; nb2 = NEGV; }

        float c0 = lae3_2(alpha[0], nb2,      skip[0] ? nb1      : NEGV);
        float c1 = lae3_2(alpha[1], alpha[0], skip[1] ? nb2      : NEGV);
        float c2 = lae3_2(alpha[2], alpha[1], skip[2] ? alpha[0] : NEGV);

        if (t < pl && t < T_) {
            alpha[0] = valid[0] ? (c0 + l0) : NEGV;
            alpha[1] = valid[1] ? (c1 + l1) : NEGV;
            alpha[2] = valid[2] ? (c2 + l2) : NEGV;
        }
    }

    // extract alpha[end], alpha[end-1] (end = 2*tl, uniform within warp)
    const int end = 2 * tl;
    const int le = end / 3, je = end % 3;
    float v0 = __shfl_sync(FULL, alpha[0], le);
    float v1 = __shfl_sync(FULL, alpha[1], le);
    float v2 = __shfl_sync(FULL, alpha[2], le);
    float a_last = (je == 0) ? v0 : (je == 1) ? v1 : v2;

    const int ep = (end > 0) ? end - 1 : 0;
    const int lpl = ep / 3, jp = ep % 3;
    float w0 = __shfl_sync(FULL, alpha[0], lpl);
    float w1 = __shfl_sync(FULL, alpha[1], lpl);
    float w2 = __shfl_sync(FULL, alpha[2], lpl);
    float a_prev = (jp == 0) ? w0 : (jp == 1) ? w1 : w2;
    if (tl <= 0) a_prev = NEGV;

    if (lane == 0) {
        float nll = -(lae2_2(a_last, a_prev) * LN2);   // back to natural log
        if (!isfinite(nll) || nll >= 1e29f) nll = 0.0f;
        int denom = tl > 0 ? tl : 1;
        g_per_n[n] = nll / (float)denom;
    }
}

// Kernel 3: mean over N
__global__ void __launch_bounds__(64) finalize_kernel(float* __restrict__ out)
{
    const int tid = threadIdx.x;
    float v = g_per_n[tid];
    #pragma unroll
    for (int o = 16; o > 0; o >>= 1) v += __shfl_xor_sync(0xffffffffu, v, o);
    __shared__ float sw[2];
    if ((tid & 31) == 0) sw[tid >> 5] = v;
    __syncthreads();
    if (tid == 0) out[0] = (sw[0] + sw[1]) / (float)N_;
}

extern "C" void kernel_launch(void* const* d_in, const int* in_sizes, int n_in,
                              void* d_out, int out_size)
{
    const float* preds          = (const float*)d_in[0];
    const int*   targets        = (const int*)d_in[1];
    const int*   pred_lengths   = (const int*)d_in[2];
    const int*   target_lengths = (const int*)d_in[3];
    float* out = (float*)d_out;

    lse_gather_kernel<<<T_ * N_, 256>>>(preds, targets);
    ctc_forward_kernel<<<N_ / 4, 128>>>(targets, pred_lengths, target_lengths);
    finalize_kernel<<<1, 64>>>(out);
}